// round 15
// baseline (speedup 1.0000x reference)
#include <cuda_runtime.h>
#include <cuda_fp16.h>
#include <cstdint>

// ============================================================================
// out_i = || P * U(params) * s_i ||^2, 131072 states of dim 256.
// params batch-invariant -> precompute A = P*U (128x256 complex).
// Gauss/Karatsuba 3M complex GEMM, fp16 mma.sync:
//   w = c+di, s = a+bi:  k1=(a+b)c, k2=a(d-c), k3=b(c+d)
//   Re = k1-k3, Im = k1+k2;  out_m = sum_n Re^2+Im^2
//
// R15: f16 ACCUMULATION AT DOUBLE RATE. Re-analysis of R9 shows f16-acc
//  HMMA runs at rt=8 (its 37.3% tensor = exactly the rt=8 busy fraction);
//  R9 was feed-limited, not rate-limited. This round keeps R14's lean
//  persistent pipeline (best: 105.5us, 82% MMA efficiency at rt=16) and
//  switches the inner accumulation to f16 within each K=64 chunk, then
//  Gauss-combines in f16 and promotes to f32 Re/Im masters per chunk
//  (64 f32 regs, LESS than the 96-reg 3-plane f32 version).
//  New walls: MMA 42.5us, smem ~39us, DRAM 256MB. Predict qmm ~60-72us.
// ============================================================================

#define NLAYERS 3
#define NQ 8
#define NTILES 2048

// Wg[op][n][k]: op0 = Ar, op1 = Ai - Ar, op2 = Ar + Ai.  (128 n x 256 k each)
__device__ __half Wg_global[3 * 128 * 256];

// ---------------------------------------------------------------------------
__device__ __forceinline__ uint32_t smem_u32(const void* p) {
    uint32_t a;
    asm("{ .reg .u64 t; cvta.to.shared.u64 t, %1; cvt.u32.u64 %0, t; }"
        : "=r"(a) : "l"(p));
    return a;
}

__device__ __forceinline__ void ldmatrix_x4(uint32_t r[4], uint32_t addr) {
    asm volatile("ldmatrix.sync.aligned.m8n8.x4.shared.b16 {%0,%1,%2,%3}, [%4];"
                 : "=r"(r[0]), "=r"(r[1]), "=r"(r[2]), "=r"(r[3]) : "r"(addr));
}

// f16-accumulate MMA: D (f16x2 in 2 regs) = A*B + C  (rt = 8 cyc/SMSP)
__device__ __forceinline__ void mma16816_f16(uint32_t c[2], const uint32_t a[4],
                                             uint32_t b0, uint32_t b1) {
    asm volatile(
        "mma.sync.aligned.m16n8k16.row.col.f16.f16.f16.f16 "
        "{%0,%1}, {%2,%3,%4,%5}, {%6,%7}, {%0,%1};"
        : "+r"(c[0]), "+r"(c[1])
        : "r"(a[0]), "r"(a[1]), "r"(a[2]), "r"(a[3]), "r"(b0), "r"(b1));
}

__device__ __forceinline__ uint32_t hadd2u(uint32_t x, uint32_t y) {
    uint32_t z;
    asm("add.f16x2 %0, %1, %2;" : "=r"(z) : "r"(x), "r"(y));
    return z;
}
__device__ __forceinline__ uint32_t hsub2u(uint32_t x, uint32_t y) {
    uint32_t z;
    asm("sub.f16x2 %0, %1, %2;" : "=r"(z) : "r"(x), "r"(y));
    return z;
}

__device__ __forceinline__ void cp_async16(uint32_t dst, const void* src) {
    asm volatile("cp.async.cg.shared.global [%0], [%1], 16;"
                 :: "r"(dst), "l"(src) : "memory");
}
#define CP_COMMIT() asm volatile("cp.async.commit_group;" ::: "memory")
#define CP_WAIT0()  asm volatile("cp.async.wait_group 0;" ::: "memory")

// ---------------------------------------------------------------------------
// Setup: block k simulates basis state |k>; writes the 3 Karatsuba weights.
// Also zero-initializes d_out (poisoned by harness; qmm atomicAdds into it).
// ---------------------------------------------------------------------------
__global__ void build_weights_kernel(const float* __restrict__ params,
                                     float* __restrict__ out_zero) {
    __shared__ float2 st[256];
    __shared__ float g[NLAYERS * NQ][8];
    int k = blockIdx.x;
    int t = threadIdx.x;

    int zi = blockIdx.x * 256 + t;
    out_zero[zi] = 0.0f;
    out_zero[zi + 65536] = 0.0f;

    if (t < NLAYERS * NQ) {
        const float* pr = params + t * 3;
        float hx = 0.5f * pr[0], hy = 0.5f * pr[1], hz = 0.5f * pr[2];
        float cx = cosf(hx), sx = sinf(hx);
        float cy = cosf(hy), sy = sinf(hy);
        float cz = cosf(hz), sz = sinf(hz);
        float m00r =  cy * cx, m00i =  sy * sx;
        float m01r = -sy * cx, m01i = -cy * sx;
        float m10r =  sy * cx, m10i = -cy * sx;
        float m11r =  cy * cx, m11i = -sy * sx;
        g[t][0] = cz * m00r + sz * m00i;  g[t][1] = cz * m00i - sz * m00r;
        g[t][2] = cz * m01r + sz * m01i;  g[t][3] = cz * m01i - sz * m01r;
        g[t][4] = cz * m10r - sz * m10i;  g[t][5] = cz * m10i + sz * m10r;
        g[t][6] = cz * m11r - sz * m11i;  g[t][7] = cz * m11i + sz * m11r;
    }
    st[t] = make_float2(t == k ? 1.0f : 0.0f, 0.0f);
    __syncthreads();

    for (int l = 0; l < NLAYERS; l++) {
        for (int q = 0; q < NQ; q++) {
            const float* u = g[l * NQ + q];
            float u00r = u[0], u00i = u[1], u01r = u[2], u01i = u[3];
            float u10r = u[4], u10i = u[5], u11r = u[6], u11i = u[7];
            int p = 7 - q;  // qubit 0 = MSB of flat index
            if (t < 128) {
                int lo = t & ((1 << p) - 1);
                int i0 = ((t >> p) << (p + 1)) | lo;
                int i1 = i0 | (1 << p);
                float2 a0 = st[i0], a1 = st[i1];
                float2 n0, n1;
                n0.x = u00r*a0.x - u00i*a0.y + u01r*a1.x - u01i*a1.y;
                n0.y = u00r*a0.y + u00i*a0.x + u01r*a1.y + u01i*a1.x;
                n1.x = u10r*a0.x - u10i*a0.y + u11r*a1.x - u11i*a1.y;
                n1.y = u10r*a0.y + u10i*a0.x + u11r*a1.y + u11i*a1.x;
                st[i0] = n0;
                st[i1] = n1;
            }
            __syncthreads();
        }
        for (int q = 0; q < NQ; q++) {
            int pc = 7 - q;
            int pt = 7 - ((q + 1) & 7);
            if (((t >> pc) & 1) == 1 && ((t >> pt) & 1) == 0) {
                int j = t | (1 << pt);
                float2 tmp = st[t];
                st[t] = st[j];
                st[j] = tmp;
            }
            __syncthreads();
        }
    }
    if (t < 128) {
        float re = st[t].x, im = st[t].y;
        Wg_global[0 * 32768 + t * 256 + k] = __float2half_rn(re);
        Wg_global[1 * 32768 + t * 256 + k] = __float2half_rn(im - re);
        Wg_global[2 * 32768 + t * 256 + k] = __float2half_rn(re + im);
    }
}

// ---------------------------------------------------------------------------
// Persistent GEMM: grid = #SMs. Each CTA loops over m-tiles (64 rows each).
// CTA = 256 threads = 8 warps, warp grid 2(M) x 4(N), warp tile 32 x 32c.
// K = 256 in 4 chunks of 64; f16 accumulation within a chunk (hacc),
// Gauss-combined in f16 and promoted to f32 Re/Im masters per chunk.
// SMEM: A fp16 [stage(2) x op(2) x 8KB] = 32KB at 0 (op0=Sr, op1=Si);
//       B fp16 RESIDENT [chunk(4) x op(3) x 16KB] = 192KB at 32KB.
// Output: per-tile quad shfl + global atomicAdd.
// ---------------------------------------------------------------------------
static constexpr uint32_t OFF_B    = 32 * 1024;
static constexpr uint32_t DYN_SMEM = 32 * 1024 + 192 * 1024 + 1024;  // 230400

__global__ void __launch_bounds__(256, 1)
qmm_kernel(const float* __restrict__ sre, const float* __restrict__ sim,
           float* __restrict__ out) {
    extern __shared__ char smem_raw[];
    uint32_t base  = smem_u32(smem_raw);
    uint32_t abase = (base + 1023u) & ~1023u;
    char* a = smem_raw + (abase - base);

    const int tid  = threadIdx.x;
    const int wid  = tid >> 5;
    const int lane = tid & 31;
    const int wm   = wid >> 2;          // 0..1 : rows wm*32..+31
    const int wn   = wid & 3;           // 0..3 : complex cols wn*32..+31
    const int kst  = (wid & 1) << 1;    // ks stagger: even warps 0, odd 2

    // ldmatrix per-lane geometry
    const int r  = lane & 7;
    const int q  = lane >> 3;
    const uint32_t xorv = (uint32_t)r << 4;
    const uint32_t ch16 = (uint32_t)(q >> 1) << 4;
    const int rl = ((q & 1) << 3) + r;

    uint32_t aRow[2], bRow[2];
    #pragma unroll
    for (int mf = 0; mf < 2; mf++)
        aRow[mf] = abase + (uint32_t)(wm * 32 + mf * 16 + rl) * 128;
    #pragma unroll
    for (int nb = 0; nb < 2; nb++)
        bRow[nb] = abase + OFF_B + (uint32_t)(wn * 32 + nb * 16 + rl) * 128;

    // ---- B resident load (once per CTA): 12288 x 16B, 256 thr -> 48 each --
    #pragma unroll
    for (int it = 0; it < 48; it++) {
        int i = tid + it * 256;
        int c  = i / 3072;
        int rm = i % 3072;
        int op = rm >> 10;
        int j  = rm & 1023;
        int n = j >> 3, seg = j & 7;
        uint32_t dst = abase + OFF_B + (uint32_t)(c * 3 + op) * 16384u +
                       (uint32_t)n * 128 +
                       (((uint32_t)seg * 16) ^ (((uint32_t)n & 7) << 4));
        cp_async16(dst, Wg_global + op * 32768 + n * 256 + c * 64 + seg * 8);
    }
    CP_COMMIT();

    // A: per chunk 64 rows x 16 float4 per source; 256 thr -> 4 + 4 (MLP 8)
    float4 av[8];
    auto ldgA = [&](long tb, int c) {
        int kb = c * 64;
        #pragma unroll
        for (int it = 0; it < 4; it++) {
            int i = tid + it * 256;
            int row = i >> 4, f4 = i & 15;
            av[it]     = *(const float4*)(sre + (tb + row) * 256 + kb + f4 * 4);
            av[4 + it] = *(const float4*)(sim + (tb + row) * 256 + kb + f4 * 4);
        }
    };
    auto stsA = [&](int stage) {
        uint32_t stg = (uint32_t)stage * 16384u;
        #pragma unroll
        for (int it = 0; it < 4; it++) {
            int i = tid + it * 256;
            int row = i >> 4, f4 = i & 15;
            uint32_t byte = (uint32_t)row * 128 +
                            (((uint32_t)f4 * 8) ^ (((uint32_t)row & 7) << 4));
            __half2 r0 = __floats2half2_rn(av[it].x, av[it].y);
            __half2 r1 = __floats2half2_rn(av[it].z, av[it].w);
            __half2 i0 = __floats2half2_rn(av[4 + it].x, av[4 + it].y);
            __half2 i1 = __floats2half2_rn(av[4 + it].z, av[4 + it].w);
            uint2 v;
            v.x = *(const uint32_t*)&r0; v.y = *(const uint32_t*)&r1;
            *(uint2*)(a + stg + byte) = v;              // op0 = Sr
            v.x = *(const uint32_t*)&i0; v.y = *(const uint32_t*)&i1;
            *(uint2*)(a + stg + 8192 + byte) = v;       // op1 = Si
        }
    };

    // f32 masters: Re/Im per (mf, nf, i) -> 64 regs
    float accRe[2][4][4], accIm[2][4][4];
    // f16 chunk accumulators: 3 planes x 2mf x 4nf x 2 regs = 48 regs
    uint32_t hacc[3][2][4][2];

    // Plane order p1 (fr), p2 (fi), p0 (fs = HADD2(fr,fi)).
    auto compute_ks = [&](int c, int ks) {
        uint32_t cx   = (((uint32_t)ks * 32) | ch16) ^ xorv;
        uint32_t astg = (uint32_t)(c & 1) * 16384u;
        uint32_t bstg = (uint32_t)(c * 3) * 16384u;
        uint32_t fr[2][4], fi[2][4], fs[2][4];
        #pragma unroll
        for (int mf = 0; mf < 2; mf++)
            ldmatrix_x4(fr[mf], aRow[mf] + astg + cx);            // Sr
        #pragma unroll
        for (int mf = 0; mf < 2; mf++)
            ldmatrix_x4(fi[mf], aRow[mf] + astg + 8192u + cx);    // Si

        // p1: Sr x (d-c)
        {
            uint32_t bf[2][4];
            #pragma unroll
            for (int nb = 0; nb < 2; nb++)
                ldmatrix_x4(bf[nb], bRow[nb] + bstg + 16384u + cx);
            #pragma unroll
            for (int mf = 0; mf < 2; mf++)
                #pragma unroll
                for (int nf = 0; nf < 4; nf++) {
                    int nb = nf >> 1, sub = nf & 1;
                    mma16816_f16(hacc[1][mf][nf], fr[mf], bf[nb][sub], bf[nb][sub + 2]);
                }
        }
        // p2: Si x (c+d)
        {
            uint32_t bf[2][4];
            #pragma unroll
            for (int nb = 0; nb < 2; nb++)
                ldmatrix_x4(bf[nb], bRow[nb] + bstg + 32768u + cx);
            #pragma unroll
            for (int mf = 0; mf < 2; mf++)
                #pragma unroll
                for (int nf = 0; nf < 4; nf++) {
                    int nb = nf >> 1, sub = nf & 1;
                    mma16816_f16(hacc[2][mf][nf], fi[mf], bf[nb][sub], bf[nb][sub + 2]);
                }
        }
        // p0: Ssum x c
        #pragma unroll
        for (int mf = 0; mf < 2; mf++)
            #pragma unroll
            for (int j = 0; j < 4; j++)
                fs[mf][j] = hadd2u(fr[mf][j], fi[mf][j]);
        {
            uint32_t bf[2][4];
            #pragma unroll
            for (int nb = 0; nb < 2; nb++)
                ldmatrix_x4(bf[nb], bRow[nb] + bstg + cx);
            #pragma unroll
            for (int mf = 0; mf < 2; mf++)
                #pragma unroll
                for (int nf = 0; nf < 4; nf++) {
                    int nb = nf >> 1, sub = nf & 1;
                    mma16816_f16(hacc[0][mf][nf], fs[mf], bf[nb][sub], bf[nb][sub + 2]);
                }
        }
    };

    // ---- prologue: A(tile0, chunk0) into stage 0; wait for resident B ----
    const int grid = gridDim.x;
    long tile0 = blockIdx.x;
    ldgA(tile0 * 64, 0);
    stsA(0);
    CP_WAIT0();

    // ---- persistent tile loop ----
    for (long ti = tile0; ti < NTILES; ti += grid) {
        const long tb = ti * 64;
        long tnext = ti + grid;
        if (tnext >= NTILES) tnext = 0;   // clamped; results unused
        const long tbn = tnext * 64;

        #pragma unroll
        for (int mf = 0; mf < 2; mf++)
            #pragma unroll
            for (int nf = 0; nf < 4; nf++)
                #pragma unroll
                for (int i = 0; i < 4; i++) {
                    accRe[mf][nf][i] = 0.0f;
                    accIm[mf][nf][i] = 0.0f;
                }

        #pragma unroll
        for (int c = 0; c < 4; c++) {
            __syncthreads();   // A stage (c&1) visible; all warps past prior reads

            // zero f16 chunk accumulators
            #pragma unroll
            for (int p = 0; p < 3; p++)
                #pragma unroll
                for (int mf = 0; mf < 2; mf++)
                    #pragma unroll
                    for (int nf = 0; nf < 4; nf++) {
                        hacc[p][mf][nf][0] = 0u;
                        hacc[p][mf][nf][1] = 0u;
                    }

            ldgA((c < 3) ? tb : tbn, (c + 1) & 3);
            compute_ks(c, kst ^ 0);
            compute_ks(c, kst ^ 1);
            stsA((c & 1) ^ 1);
            compute_ks(c, kst ^ 2);
            compute_ks(c, kst ^ 3);

            // promote: Re += k1-k3, Im += k1+k2 (combine in f16, acc in f32)
            #pragma unroll
            for (int mf = 0; mf < 2; mf++)
                #pragma unroll
                for (int nf = 0; nf < 4; nf++) {
                    #pragma unroll
                    for (int h = 0; h < 2; h++) {
                        uint32_t reh = hsub2u(hacc[0][mf][nf][h], hacc[2][mf][nf][h]);
                        uint32_t imh = hadd2u(hacc[0][mf][nf][h], hacc[1][mf][nf][h]);
                        float2 ref = __half22float2(*(const __half2*)&reh);
                        float2 imf = __half22float2(*(const __half2*)&imh);
                        accRe[mf][nf][h * 2]     += ref.x;
                        accRe[mf][nf][h * 2 + 1] += ref.y;
                        accIm[mf][nf][h * 2]     += imf.x;
                        accIm[mf][nf][h * 2 + 1] += imf.y;
                    }
                }
        }

        // ---- per-tile epilogue: out[m] += sum Re^2+Im^2 ----
        #pragma unroll
        for (int mf = 0; mf < 2; mf++) {
            float s_lo = 0.0f, s_hi = 0.0f;
            #pragma unroll
            for (int nf = 0; nf < 4; nf++) {
                #pragma unroll
                for (int i = 0; i < 4; i++) {
                    float re = accRe[mf][nf][i];
                    float im = accIm[mf][nf][i];
                    float v = fmaf(re, re, im * im);
                    if (i < 2) s_lo += v; else s_hi += v;
                }
            }
            s_lo += __shfl_xor_sync(0xFFFFFFFF, s_lo, 1);
            s_lo += __shfl_xor_sync(0xFFFFFFFF, s_lo, 2);
            s_hi += __shfl_xor_sync(0xFFFFFFFF, s_hi, 1);
            s_hi += __shfl_xor_sync(0xFFFFFFFF, s_hi, 2);
            if ((lane & 3) == 0) {
                long row = tb + wm * 32 + mf * 16 + (lane >> 2);
                atomicAdd(out + row, s_lo);
                atomicAdd(out + row + 8, s_hi);
            }
        }
    }
}

// ---------------------------------------------------------------------------
extern "C" void kernel_launch(void* const* d_in, const int* in_sizes, int n_in,
                              void* d_out, int out_size) {
    const float* params = (const float*)d_in[0];
    const float* sre    = (const float*)d_in[1];
    const float* sim    = (const float*)d_in[2];
    float* out = (float*)d_out;

    cudaFuncSetAttribute(qmm_kernel, cudaFuncAttributeMaxDynamicSharedMemorySize,
                         DYN_SMEM);

    int nsm = 148;
    cudaDeviceGetAttribute(&nsm, cudaDevAttrMultiProcessorCount, 0);
    if (nsm < 1) nsm = 148;

    build_weights_kernel<<<256, 256>>>(params, out);
    qmm_kernel<<<nsm, 256, DYN_SMEM>>>(sre, sim, out);
}

// round 16
// speedup vs baseline: 1.0061x; 1.0061x over previous
#include <cuda_runtime.h>
#include <cuda_fp16.h>
#include <cstdint>

// ============================================================================
// out_i = || P * U(params) * s_i ||^2, 131072 states of dim 256.
// params batch-invariant -> precompute A = P*U (128x256 complex).
// Gauss/Karatsuba 3M complex GEMM, fp16 mma.sync with f16 accumulation
// (CONFIRMED double-rate: R9 37.3% and R15 35.5% tensor busy = exactly the
// rt=8 fraction), chunk-local (K=64) f16 acc -> f32 promotion.
//   w = c+di, s = a+bi:  k1=(a+b)c, k2=a(d-c), k3=b(c+d)
//   Re = k1-k3, Im = k1+k2;  out_m = sum_n Re^2+Im^2
//
// R16: PLANE-OUTER + STREAMING COMBINE (fixes R15's 255-reg spill collapse).
//  Per chunk, planes run sequentially, each with ONE 16-reg f16 hacc:
//    p1: Sr x (d-c)  -> accIm += k2
//    p2: Si x (c+d)  -> accRe -= k3
//    p0: Ssum x c    -> accRe += k1; accIm += k1   (Ssum via HADD2)
//  Masters = just Re/Im f32 (64 regs). Est total ~175 regs, no spills.
//  Walls: MMA 43us (rt=8), L1 ~2176 wf/chunk -> ~62us. Predict qmm 65-78us.
//  Persistent skeleton unchanged (grid=#SMs, B 192KB resident, A dbl-buf).
// ============================================================================

#define NLAYERS 3
#define NQ 8
#define NTILES 2048

// Wg[op][n][k]: op0 = Ar, op1 = Ai - Ar, op2 = Ar + Ai.  (128 n x 256 k each)
__device__ __half Wg_global[3 * 128 * 256];

// ---------------------------------------------------------------------------
__device__ __forceinline__ uint32_t smem_u32(const void* p) {
    uint32_t a;
    asm("{ .reg .u64 t; cvta.to.shared.u64 t, %1; cvt.u32.u64 %0, t; }"
        : "=r"(a) : "l"(p));
    return a;
}

__device__ __forceinline__ void ldmatrix_x4(uint32_t r[4], uint32_t addr) {
    asm volatile("ldmatrix.sync.aligned.m8n8.x4.shared.b16 {%0,%1,%2,%3}, [%4];"
                 : "=r"(r[0]), "=r"(r[1]), "=r"(r[2]), "=r"(r[3]) : "r"(addr));
}

// f16-accumulate MMA: D (f16x2 in 2 regs) = A*B + C  (rt = 8 cyc/SMSP)
__device__ __forceinline__ void mma16816_f16(uint32_t c[2], const uint32_t a[4],
                                             uint32_t b0, uint32_t b1) {
    asm volatile(
        "mma.sync.aligned.m16n8k16.row.col.f16.f16.f16.f16 "
        "{%0,%1}, {%2,%3,%4,%5}, {%6,%7}, {%0,%1};"
        : "+r"(c[0]), "+r"(c[1])
        : "r"(a[0]), "r"(a[1]), "r"(a[2]), "r"(a[3]), "r"(b0), "r"(b1));
}

__device__ __forceinline__ uint32_t hadd2u(uint32_t x, uint32_t y) {
    uint32_t z;
    asm("add.f16x2 %0, %1, %2;" : "=r"(z) : "r"(x), "r"(y));
    return z;
}

__device__ __forceinline__ void cp_async16(uint32_t dst, const void* src) {
    asm volatile("cp.async.cg.shared.global [%0], [%1], 16;"
                 :: "r"(dst), "l"(src) : "memory");
}
#define CP_COMMIT() asm volatile("cp.async.commit_group;" ::: "memory")
#define CP_WAIT0()  asm volatile("cp.async.wait_group 0;" ::: "memory")

// ---------------------------------------------------------------------------
// Setup: block k simulates basis state |k>; writes the 3 Karatsuba weights.
// Also zero-initializes d_out (poisoned by harness; qmm atomicAdds into it).
// ---------------------------------------------------------------------------
__global__ void build_weights_kernel(const float* __restrict__ params,
                                     float* __restrict__ out_zero) {
    __shared__ float2 st[256];
    __shared__ float g[NLAYERS * NQ][8];
    int k = blockIdx.x;
    int t = threadIdx.x;

    int zi = blockIdx.x * 256 + t;
    out_zero[zi] = 0.0f;
    out_zero[zi + 65536] = 0.0f;

    if (t < NLAYERS * NQ) {
        const float* pr = params + t * 3;
        float hx = 0.5f * pr[0], hy = 0.5f * pr[1], hz = 0.5f * pr[2];
        float cx = cosf(hx), sx = sinf(hx);
        float cy = cosf(hy), sy = sinf(hy);
        float cz = cosf(hz), sz = sinf(hz);
        float m00r =  cy * cx, m00i =  sy * sx;
        float m01r = -sy * cx, m01i = -cy * sx;
        float m10r =  sy * cx, m10i = -cy * sx;
        float m11r =  cy * cx, m11i = -sy * sx;
        g[t][0] = cz * m00r + sz * m00i;  g[t][1] = cz * m00i - sz * m00r;
        g[t][2] = cz * m01r + sz * m01i;  g[t][3] = cz * m01i - sz * m01r;
        g[t][4] = cz * m10r - sz * m10i;  g[t][5] = cz * m10i + sz * m10r;
        g[t][6] = cz * m11r - sz * m11i;  g[t][7] = cz * m11i + sz * m11r;
    }
    st[t] = make_float2(t == k ? 1.0f : 0.0f, 0.0f);
    __syncthreads();

    for (int l = 0; l < NLAYERS; l++) {
        for (int q = 0; q < NQ; q++) {
            const float* u = g[l * NQ + q];
            float u00r = u[0], u00i = u[1], u01r = u[2], u01i = u[3];
            float u10r = u[4], u10i = u[5], u11r = u[6], u11i = u[7];
            int p = 7 - q;  // qubit 0 = MSB of flat index
            if (t < 128) {
                int lo = t & ((1 << p) - 1);
                int i0 = ((t >> p) << (p + 1)) | lo;
                int i1 = i0 | (1 << p);
                float2 a0 = st[i0], a1 = st[i1];
                float2 n0, n1;
                n0.x = u00r*a0.x - u00i*a0.y + u01r*a1.x - u01i*a1.y;
                n0.y = u00r*a0.y + u00i*a0.x + u01r*a1.y + u01i*a1.x;
                n1.x = u10r*a0.x - u10i*a0.y + u11r*a1.x - u11i*a1.y;
                n1.y = u10r*a0.y + u10i*a0.x + u11r*a1.y + u11i*a1.x;
                st[i0] = n0;
                st[i1] = n1;
            }
            __syncthreads();
        }
        for (int q = 0; q < NQ; q++) {
            int pc = 7 - q;
            int pt = 7 - ((q + 1) & 7);
            if (((t >> pc) & 1) == 1 && ((t >> pt) & 1) == 0) {
                int j = t | (1 << pt);
                float2 tmp = st[t];
                st[t] = st[j];
                st[j] = tmp;
            }
            __syncthreads();
        }
    }
    if (t < 128) {
        float re = st[t].x, im = st[t].y;
        Wg_global[0 * 32768 + t * 256 + k] = __float2half_rn(re);
        Wg_global[1 * 32768 + t * 256 + k] = __float2half_rn(im - re);
        Wg_global[2 * 32768 + t * 256 + k] = __float2half_rn(re + im);
    }
}

// ---------------------------------------------------------------------------
// Persistent GEMM: grid = #SMs. Each CTA loops over m-tiles (64 rows each).
// CTA = 256 threads = 8 warps, warp grid 2(M) x 4(N), warp tile 32 x 32c.
// K = 256 in 4 chunks of 64; per chunk the 3 Gauss planes run SEQUENTIALLY,
// each into one 16-reg f16 accumulator, streamed into f32 Re/Im masters.
// SMEM: A fp16 [stage(2) x op(2) x 8KB] = 32KB at 0 (op0=Sr, op1=Si);
//       B fp16 RESIDENT [chunk(4) x op(3) x 16KB] = 192KB at 32KB.
// Output: per-tile quad shfl + global atomicAdd.
// ---------------------------------------------------------------------------
static constexpr uint32_t OFF_B    = 32 * 1024;
static constexpr uint32_t DYN_SMEM = 32 * 1024 + 192 * 1024 + 1024;  // 230400

__global__ void __launch_bounds__(256, 1)
qmm_kernel(const float* __restrict__ sre, const float* __restrict__ sim,
           float* __restrict__ out) {
    extern __shared__ char smem_raw[];
    uint32_t base  = smem_u32(smem_raw);
    uint32_t abase = (base + 1023u) & ~1023u;
    char* a = smem_raw + (abase - base);

    const int tid  = threadIdx.x;
    const int wid  = tid >> 5;
    const int lane = tid & 31;
    const int wm   = wid >> 2;          // 0..1 : rows wm*32..+31
    const int wn   = wid & 3;           // 0..3 : complex cols wn*32..+31
    const int kst  = (wid & 1) << 1;    // ks stagger: even warps 0, odd 2

    // ldmatrix per-lane geometry
    const int r  = lane & 7;
    const int q  = lane >> 3;
    const uint32_t xorv = (uint32_t)r << 4;
    const uint32_t ch16 = (uint32_t)(q >> 1) << 4;
    const int rl = ((q & 1) << 3) + r;

    uint32_t aRow[2], bRow[2];
    #pragma unroll
    for (int mf = 0; mf < 2; mf++)
        aRow[mf] = abase + (uint32_t)(wm * 32 + mf * 16 + rl) * 128;
    #pragma unroll
    for (int nb = 0; nb < 2; nb++)
        bRow[nb] = abase + OFF_B + (uint32_t)(wn * 32 + nb * 16 + rl) * 128;

    // ---- B resident load (once per CTA): 12288 x 16B, 256 thr -> 48 each --
    #pragma unroll
    for (int it = 0; it < 48; it++) {
        int i = tid + it * 256;
        int c  = i / 3072;
        int rm = i % 3072;
        int op = rm >> 10;
        int j  = rm & 1023;
        int n = j >> 3, seg = j & 7;
        uint32_t dst = abase + OFF_B + (uint32_t)(c * 3 + op) * 16384u +
                       (uint32_t)n * 128 +
                       (((uint32_t)seg * 16) ^ (((uint32_t)n & 7) << 4));
        cp_async16(dst, Wg_global + op * 32768 + n * 256 + c * 64 + seg * 8);
    }
    CP_COMMIT();

    // A: per chunk 64 rows x 16 float4 per source; 256 thr -> 4 + 4 (MLP 8)
    float4 av[8];
    auto ldgA = [&](long tb, int c) {
        int kb = c * 64;
        #pragma unroll
        for (int it = 0; it < 4; it++) {
            int i = tid + it * 256;
            int row = i >> 4, f4 = i & 15;
            av[it]     = *(const float4*)(sre + (tb + row) * 256 + kb + f4 * 4);
            av[4 + it] = *(const float4*)(sim + (tb + row) * 256 + kb + f4 * 4);
        }
    };
    auto stsA = [&](int stage) {
        uint32_t stg = (uint32_t)stage * 16384u;
        #pragma unroll
        for (int it = 0; it < 4; it++) {
            int i = tid + it * 256;
            int row = i >> 4, f4 = i & 15;
            uint32_t byte = (uint32_t)row * 128 +
                            (((uint32_t)f4 * 8) ^ (((uint32_t)row & 7) << 4));
            __half2 r0 = __floats2half2_rn(av[it].x, av[it].y);
            __half2 r1 = __floats2half2_rn(av[it].z, av[it].w);
            __half2 i0 = __floats2half2_rn(av[4 + it].x, av[4 + it].y);
            __half2 i1 = __floats2half2_rn(av[4 + it].z, av[4 + it].w);
            uint2 v;
            v.x = *(const uint32_t*)&r0; v.y = *(const uint32_t*)&r1;
            *(uint2*)(a + stg + byte) = v;              // op0 = Sr
            v.x = *(const uint32_t*)&i0; v.y = *(const uint32_t*)&i1;
            *(uint2*)(a + stg + 8192 + byte) = v;       // op1 = Si
        }
    };

    // f32 masters: Re/Im per (mf, nf, i) -> 64 regs. Streaming Gauss combine.
    float accRe[2][4][4], accIm[2][4][4];
    // ONE f16 chunk accumulator (16 regs), reused across the 3 planes.
    uint32_t hacc[2][4][2];

    auto zero_hacc = [&]() {
        #pragma unroll
        for (int mf = 0; mf < 2; mf++)
            #pragma unroll
            for (int nf = 0; nf < 4; nf++) {
                hacc[mf][nf][0] = 0u;
                hacc[mf][nf][1] = 0u;
            }
    };

    // One plane over a chunk: aSel 0=Sr, 1=Si, 2=Ssum(HADD2); bOp 0/1/2.
    auto run_plane = [&](int c, int aSel, int bOp) {
        uint32_t astg = (uint32_t)(c & 1) * 16384u;
        uint32_t boff = (uint32_t)(c * 3 + bOp) * 16384u;
        #pragma unroll
        for (int ksi = 0; ksi < 4; ksi++) {
            int ks = kst ^ ksi;
            uint32_t cx = (((uint32_t)ks * 32) | ch16) ^ xorv;
            uint32_t af[2][4];
            if (aSel == 0) {
                #pragma unroll
                for (int mf = 0; mf < 2; mf++)
                    ldmatrix_x4(af[mf], aRow[mf] + astg + cx);
            } else if (aSel == 1) {
                #pragma unroll
                for (int mf = 0; mf < 2; mf++)
                    ldmatrix_x4(af[mf], aRow[mf] + astg + 8192u + cx);
            } else {
                #pragma unroll
                for (int mf = 0; mf < 2; mf++) {
                    uint32_t fr[4], fi[4];
                    ldmatrix_x4(fr, aRow[mf] + astg + cx);
                    ldmatrix_x4(fi, aRow[mf] + astg + 8192u + cx);
                    #pragma unroll
                    for (int j = 0; j < 4; j++)
                        af[mf][j] = hadd2u(fr[j], fi[j]);
                }
            }
            uint32_t bf[2][4];
            #pragma unroll
            for (int nb = 0; nb < 2; nb++)
                ldmatrix_x4(bf[nb], bRow[nb] + boff + cx);
            #pragma unroll
            for (int mf = 0; mf < 2; mf++)
                #pragma unroll
                for (int nf = 0; nf < 4; nf++) {
                    int nb = nf >> 1, sub = nf & 1;
                    mma16816_f16(hacc[mf][nf], af[mf], bf[nb][sub], bf[nb][sub + 2]);
                }
        }
    };

    // mode 0: accIm += k   (p1)
    // mode 1: accRe -= k   (p2)
    // mode 2: accRe += k; accIm += k   (p0)
    auto promote = [&](int mode) {
        #pragma unroll
        for (int mf = 0; mf < 2; mf++)
            #pragma unroll
            for (int nf = 0; nf < 4; nf++)
                #pragma unroll
                for (int h = 0; h < 2; h++) {
                    float2 v = __half22float2(*(const __half2*)&hacc[mf][nf][h]);
                    if (mode == 0) {
                        accIm[mf][nf][h * 2]     += v.x;
                        accIm[mf][nf][h * 2 + 1] += v.y;
                    } else if (mode == 1) {
                        accRe[mf][nf][h * 2]     -= v.x;
                        accRe[mf][nf][h * 2 + 1] -= v.y;
                    } else {
                        accRe[mf][nf][h * 2]     += v.x;
                        accRe[mf][nf][h * 2 + 1] += v.y;
                        accIm[mf][nf][h * 2]     += v.x;
                        accIm[mf][nf][h * 2 + 1] += v.y;
                    }
                }
    };

    // ---- prologue: A(tile0, chunk0) into stage 0; wait for resident B ----
    const int grid = gridDim.x;
    long tile0 = blockIdx.x;
    ldgA(tile0 * 64, 0);
    stsA(0);
    CP_WAIT0();

    // ---- persistent tile loop ----
    for (long ti = tile0; ti < NTILES; ti += grid) {
        const long tb = ti * 64;
        long tnext = ti + grid;
        if (tnext >= NTILES) tnext = 0;   // clamped; results unused
        const long tbn = tnext * 64;

        #pragma unroll
        for (int mf = 0; mf < 2; mf++)
            #pragma unroll
            for (int nf = 0; nf < 4; nf++)
                #pragma unroll
                for (int i = 0; i < 4; i++) {
                    accRe[mf][nf][i] = 0.0f;
                    accIm[mf][nf][i] = 0.0f;
                }

        #pragma unroll
        for (int c = 0; c < 4; c++) {
            __syncthreads();   // A stage (c&1) visible; all warps past prior reads

            ldgA((c < 3) ? tb : tbn, (c + 1) & 3);

            zero_hacc();
            run_plane(c, 0, 1);   // p1: Sr x (d-c)
            promote(0);           // accIm += k2

            zero_hacc();
            run_plane(c, 1, 2);   // p2: Si x (c+d)
            promote(1);           // accRe -= k3

            stsA((c & 1) ^ 1);

            zero_hacc();
            run_plane(c, 2, 0);   // p0: Ssum x c
            promote(2);           // accRe += k1; accIm += k1
        }

        // ---- per-tile epilogue: out[m] += sum Re^2+Im^2 ----
        #pragma unroll
        for (int mf = 0; mf < 2; mf++) {
            float s_lo = 0.0f, s_hi = 0.0f;
            #pragma unroll
            for (int nf = 0; nf < 4; nf++) {
                #pragma unroll
                for (int i = 0; i < 4; i++) {
                    float re = accRe[mf][nf][i];
                    float im = accIm[mf][nf][i];
                    float v = fmaf(re, re, im * im);
                    if (i < 2) s_lo += v; else s_hi += v;
                }
            }
            s_lo += __shfl_xor_sync(0xFFFFFFFF, s_lo, 1);
            s_lo += __shfl_xor_sync(0xFFFFFFFF, s_lo, 2);
            s_hi += __shfl_xor_sync(0xFFFFFFFF, s_hi, 1);
            s_hi += __shfl_xor_sync(0xFFFFFFFF, s_hi, 2);
            if ((lane & 3) == 0) {
                long row = tb + wm * 32 + mf * 16 + (lane >> 2);
                atomicAdd(out + row, s_lo);
                atomicAdd(out + row + 8, s_hi);
            }
        }
    }
}

// ---------------------------------------------------------------------------
extern "C" void kernel_launch(void* const* d_in, const int* in_sizes, int n_in,
                              void* d_out, int out_size) {
    const float* params = (const float*)d_in[0];
    const float* sre    = (const float*)d_in[1];
    const float* sim    = (const float*)d_in[2];
    float* out = (float*)d_out;

    cudaFuncSetAttribute(qmm_kernel, cudaFuncAttributeMaxDynamicSharedMemorySize,
                         DYN_SMEM);

    int nsm = 148;
    cudaDeviceGetAttribute(&nsm, cudaDevAttrMultiProcessorCount, 0);
    if (nsm < 1) nsm = 148;

    build_weights_kernel<<<256, 256>>>(params, out);
    qmm_kernel<<<nsm, 256, DYN_SMEM>>>(sre, sim, out);
}